// round 1
// baseline (speedup 1.0000x reference)
#include <cuda_runtime.h>
#include <cuda_bf16.h>

// Problem dimensions (fixed by the reference)
constexpr int B_  = 4;
constexpr int N_  = 4096;
constexpr int M_  = 1024;
constexpr int QD_ = 320;
constexpr int CD_ = 768;
constexpr int ID_ = 512;
constexpr int H_  = 8;
constexpr int D_  = 64;
constexpr float SCALE_ = 0.125f;  // 64^-0.5

// Scratch (device globals; allocation inside kernel_launch is forbidden)
__device__ float g_q [(size_t)B_ * N_ * ID_];   // 33.5 MB
__device__ float g_k [(size_t)B_ * M_ * ID_];   //  8.4 MB
__device__ float g_v [(size_t)B_ * M_ * ID_];   //  8.4 MB
__device__ float g_ao[(size_t)B_ * N_ * ID_];   // 33.5 MB

// ---------------------------------------------------------------------------
// Tiled fp32 GEMM: C[M,N] = A[M,K] @ B[K,N] (+ bias)
// 256 threads (16x16), BK=16, each thread computes TM x TN.
// Requires: M % BM == 0, N % BN == 0, K % 16 == 0 (true for all our shapes).
// B-columns per thread split into TN/4 groups of 4 for conflict-free float4 reads.
// ---------------------------------------------------------------------------
template<int BM, int BN, int TM, int TN, bool BIAS>
__global__ __launch_bounds__(256) void gemm_kernel(
    const float* __restrict__ A, const float* __restrict__ Bm,
    const float* __restrict__ bias, float* __restrict__ C,
    int Mdim, int Ndim, int Kdim)
{
    constexpr int G = TN / 4;            // column groups per thread
    __shared__ float As[16][BM];         // A tile, transposed: As[k][m]
    __shared__ float Bs[16][BN];         // B tile: Bs[k][n]

    const int tid = threadIdx.x;
    const int ty = tid >> 4;             // 0..15
    const int tx = tid & 15;             // 0..15
    const int bm0 = blockIdx.y * BM;
    const int bn0 = blockIdx.x * BN;

    float acc[TM][TN];
    #pragma unroll
    for (int i = 0; i < TM; i++)
        #pragma unroll
        for (int j = 0; j < TN; j++) acc[i][j] = 0.0f;

    for (int k0 = 0; k0 < Kdim; k0 += 16) {
        // Load A tile (BM x 16) -> transposed smem
        for (int i = tid; i < BM * 4; i += 256) {
            int r  = i >> 2;
            int c4 = i & 3;
            float4 v = *(const float4*)(A + (size_t)(bm0 + r) * Kdim + k0 + c4 * 4);
            As[c4 * 4 + 0][r] = v.x;
            As[c4 * 4 + 1][r] = v.y;
            As[c4 * 4 + 2][r] = v.z;
            As[c4 * 4 + 3][r] = v.w;
        }
        // Load B tile (16 x BN)
        for (int i = tid; i < BN * 4; i += 256) {
            int r = i / (BN / 4);
            int c = i - r * (BN / 4);
            *(float4*)&Bs[r][c * 4] =
                *(const float4*)(Bm + (size_t)(k0 + r) * Ndim + bn0 + c * 4);
        }
        __syncthreads();

        #pragma unroll 4
        for (int k = 0; k < 16; k++) {
            float a[TM], bb[TN];
            #pragma unroll
            for (int t = 0; t < TM / 4; t++) {
                float4 v = *(const float4*)&As[k][ty * TM + t * 4];
                a[t * 4 + 0] = v.x; a[t * 4 + 1] = v.y;
                a[t * 4 + 2] = v.z; a[t * 4 + 3] = v.w;
            }
            #pragma unroll
            for (int g = 0; g < G; g++) {
                float4 v = *(const float4*)&Bs[k][g * (BN / G) + tx * 4];
                bb[g * 4 + 0] = v.x; bb[g * 4 + 1] = v.y;
                bb[g * 4 + 2] = v.z; bb[g * 4 + 3] = v.w;
            }
            #pragma unroll
            for (int ii = 0; ii < TM; ii++)
                #pragma unroll
                for (int jj = 0; jj < TN; jj++)
                    acc[ii][jj] = fmaf(a[ii], bb[jj], acc[ii][jj]);
        }
        __syncthreads();
    }

    // Epilogue
    #pragma unroll
    for (int ii = 0; ii < TM; ii++) {
        int row = bm0 + ty * TM + ii;
        #pragma unroll
        for (int g = 0; g < G; g++) {
            int col = bn0 + g * (BN / G) + tx * 4;
            float4 r;
            r.x = acc[ii][g * 4 + 0];
            r.y = acc[ii][g * 4 + 1];
            r.z = acc[ii][g * 4 + 2];
            r.w = acc[ii][g * 4 + 3];
            if (BIAS) {
                r.x += bias[col + 0];
                r.y += bias[col + 1];
                r.z += bias[col + 2];
                r.w += bias[col + 3];
            }
            *(float4*)(C + (size_t)row * Ndim + col) = r;
        }
    }
}

// ---------------------------------------------------------------------------
// Flash attention, fp32. One block = 64 query rows of one (b, h).
// 256 threads (16x16); each thread owns a 4x4 of S/P and a 4x4 of O (d-cols).
// Q/K/V layouts: [B*rows, ID] with head h at column offset h*64.
// K staged d-major (transposed) in smem -> conflict-free float4 reads in S loop.
// ---------------------------------------------------------------------------
constexpr int FLASH_SMEM = (64 * 64 + 3 * 64 * 68) * 4;   // 68608 bytes

__global__ __launch_bounds__(256) void flash_kernel(
    const float* __restrict__ Q, const float* __restrict__ K,
    const float* __restrict__ V, float* __restrict__ O)
{
    extern __shared__ float sm[];
    float* Qs  = sm;                    // [64][64]  (q rows x d), pre-scaled
    float* Kst = sm + 64 * 64;          // [64][68]  (d x key)  transposed
    float* Vs  = Kst + 64 * 68;         // [64][68]  (key x d)
    float* Ps  = Vs + 64 * 68;          // [64][68]  (q row x key)

    const int tid = threadIdx.x;
    const int ty = tid >> 4, tx = tid & 15;
    const int row0 = ty * 4, col0 = tx * 4;
    const int n0 = blockIdx.x * 64;
    const int h = blockIdx.y;
    const int b = blockIdx.z;

    // Load Q tile (64 x 64), fold in softmax scale
    const float* qbase = Q + ((size_t)(b * N_ + n0)) * ID_ + h * 64;
    for (int i = tid; i < 1024; i += 256) {
        int r = i >> 4, c4 = i & 15;
        float4 v = *(const float4*)(qbase + (size_t)r * ID_ + c4 * 4);
        v.x *= SCALE_; v.y *= SCALE_; v.z *= SCALE_; v.w *= SCALE_;
        *(float4*)(Qs + r * 64 + c4 * 4) = v;
    }

    float m[4], l[4], o[4][4];
    #pragma unroll
    for (int i = 0; i < 4; i++) {
        m[i] = -3.0e38f; l[i] = 0.0f;
        #pragma unroll
        for (int j = 0; j < 4; j++) o[i][j] = 0.0f;
    }

    const float* kbase = K + ((size_t)(b * M_)) * ID_ + h * 64;
    const float* vbase = V + ((size_t)(b * M_)) * ID_ + h * 64;

    for (int kt = 0; kt < M_ / 64; kt++) {
        __syncthreads();   // protect prev-iter reads of Kst/Vs/Ps
        const int ks0 = kt * 64;
        // Load K tile transposed (d-major) + V tile (row-major)
        for (int i = tid; i < 1024; i += 256) {
            int r = i >> 4, c4 = i & 15;
            float4 kv = *(const float4*)(kbase + (size_t)(ks0 + r) * ID_ + c4 * 4);
            Kst[(c4 * 4 + 0) * 68 + r] = kv.x;
            Kst[(c4 * 4 + 1) * 68 + r] = kv.y;
            Kst[(c4 * 4 + 2) * 68 + r] = kv.z;
            Kst[(c4 * 4 + 3) * 68 + r] = kv.w;
            float4 vv = *(const float4*)(vbase + (size_t)(ks0 + r) * ID_ + c4 * 4);
            *(float4*)(Vs + r * 68 + c4 * 4) = vv;
        }
        __syncthreads();

        // S = Q @ K^T (scaled already)
        float S[4][4];
        #pragma unroll
        for (int i = 0; i < 4; i++)
            #pragma unroll
            for (int j = 0; j < 4; j++) S[i][j] = 0.0f;

        #pragma unroll 2
        for (int d4 = 0; d4 < 16; d4++) {
            float qa[4][4];
            #pragma unroll
            for (int i = 0; i < 4; i++) {
                float4 v = *(const float4*)(Qs + (row0 + i) * 64 + d4 * 4);
                qa[i][0] = v.x; qa[i][1] = v.y; qa[i][2] = v.z; qa[i][3] = v.w;
            }
            #pragma unroll
            for (int dd = 0; dd < 4; dd++) {
                float4 kv = *(const float4*)(Kst + (d4 * 4 + dd) * 68 + col0);
                float kb0 = kv.x, kb1 = kv.y, kb2 = kv.z, kb3 = kv.w;
                #pragma unroll
                for (int i = 0; i < 4; i++) {
                    S[i][0] = fmaf(qa[i][dd], kb0, S[i][0]);
                    S[i][1] = fmaf(qa[i][dd], kb1, S[i][1]);
                    S[i][2] = fmaf(qa[i][dd], kb2, S[i][2]);
                    S[i][3] = fmaf(qa[i][dd], kb3, S[i][3]);
                }
            }
        }

        // Online softmax update (row-wise over the 16 tx lanes)
        #pragma unroll
        for (int i = 0; i < 4; i++) {
            float tm = fmaxf(fmaxf(S[i][0], S[i][1]), fmaxf(S[i][2], S[i][3]));
            #pragma unroll
            for (int off = 8; off >= 1; off >>= 1)
                tm = fmaxf(tm, __shfl_xor_sync(0xffffffffu, tm, off, 16));
            float mn = fmaxf(m[i], tm);
            float alpha = __expf(m[i] - mn);
            m[i] = mn;
            float rs = 0.0f;
            #pragma unroll
            for (int j = 0; j < 4; j++) {
                S[i][j] = __expf(S[i][j] - mn);
                rs += S[i][j];
            }
            #pragma unroll
            for (int off = 8; off >= 1; off >>= 1)
                rs += __shfl_xor_sync(0xffffffffu, rs, off, 16);
            l[i] = l[i] * alpha + rs;
            #pragma unroll
            for (int j = 0; j < 4; j++) o[i][j] *= alpha;
            *(float4*)(Ps + (row0 + i) * 68 + col0) =
                make_float4(S[i][0], S[i][1], S[i][2], S[i][3]);
        }
        __syncthreads();

        // O += P @ V
        #pragma unroll 2
        for (int k4 = 0; k4 < 16; k4++) {
            float pa[4][4];
            #pragma unroll
            for (int i = 0; i < 4; i++) {
                float4 v = *(const float4*)(Ps + (row0 + i) * 68 + k4 * 4);
                pa[i][0] = v.x; pa[i][1] = v.y; pa[i][2] = v.z; pa[i][3] = v.w;
            }
            #pragma unroll
            for (int kk = 0; kk < 4; kk++) {
                float4 vv = *(const float4*)(Vs + (k4 * 4 + kk) * 68 + col0);
                float vb0 = vv.x, vb1 = vv.y, vb2 = vv.z, vb3 = vv.w;
                #pragma unroll
                for (int i = 0; i < 4; i++) {
                    o[i][0] = fmaf(pa[i][kk], vb0, o[i][0]);
                    o[i][1] = fmaf(pa[i][kk], vb1, o[i][1]);
                    o[i][2] = fmaf(pa[i][kk], vb2, o[i][2]);
                    o[i][3] = fmaf(pa[i][kk], vb3, o[i][3]);
                }
            }
        }
    }

    // Normalize and store
    float* obase = O + ((size_t)(b * N_ + n0)) * ID_ + h * 64;
    #pragma unroll
    for (int i = 0; i < 4; i++) {
        float inv = 1.0f / l[i];
        *(float4*)(obase + (size_t)(row0 + i) * ID_ + col0) =
            make_float4(o[i][0] * inv, o[i][1] * inv, o[i][2] * inv, o[i][3] * inv);
    }
}

// ---------------------------------------------------------------------------
// Launch
// ---------------------------------------------------------------------------
extern "C" void kernel_launch(void* const* d_in, const int* in_sizes, int n_in,
                              void* d_out, int out_size)
{
    const float* x   = (const float*)d_in[0];  // [4,4096,320]
    const float* ctx = (const float*)d_in[1];  // [4,1024,768]
    const float* Wq  = (const float*)d_in[2];  // [320,512]
    const float* Wk  = (const float*)d_in[3];  // [768,512]
    const float* Wv  = (const float*)d_in[4];  // [768,512]
    const float* Wo  = (const float*)d_in[5];  // [512,320]
    const float* bo  = (const float*)d_in[6];  // [320]
    float* out = (float*)d_out;                // [4,4096,320]

    void *pq, *pk, *pv, *pao;
    cudaGetSymbolAddress(&pq,  g_q);
    cudaGetSymbolAddress(&pk,  g_k);
    cudaGetSymbolAddress(&pv,  g_v);
    cudaGetSymbolAddress(&pao, g_ao);
    float* q  = (float*)pq;
    float* k  = (float*)pk;
    float* v  = (float*)pv;
    float* ao = (float*)pao;

    cudaFuncSetAttribute(flash_kernel,
                         cudaFuncAttributeMaxDynamicSharedMemorySize, FLASH_SMEM);

    // q = x @ Wq : [16384,320]x[320,512]
    gemm_kernel<128, 128, 8, 8, false><<<dim3(ID_ / 128, (B_ * N_) / 128), 256>>>(
        x, Wq, nullptr, q, B_ * N_, ID_, QD_);
    // k = ctx @ Wk : [4096,768]x[768,512]
    gemm_kernel<128, 128, 8, 8, false><<<dim3(ID_ / 128, (B_ * M_) / 128), 256>>>(
        ctx, Wk, nullptr, k, B_ * M_, ID_, CD_);
    // v = ctx @ Wv
    gemm_kernel<128, 128, 8, 8, false><<<dim3(ID_ / 128, (B_ * M_) / 128), 256>>>(
        ctx, Wv, nullptr, v, B_ * M_, ID_, CD_);
    // attention
    flash_kernel<<<dim3(N_ / 64, H_, B_), 256, FLASH_SMEM>>>(q, k, v, ao);
    // out = ao @ Wo + bo : [16384,512]x[512,320]
    gemm_kernel<128, 64, 8, 4, true><<<dim3(QD_ / 64, (B_ * N_) / 128), 256>>>(
        ao, Wo, bo, out, B_ * N_, QD_, ID_);
}

// round 2
// speedup vs baseline: 2.2596x; 2.2596x over previous
#include <cuda_runtime.h>
#include <cuda_bf16.h>
#include <cstdint>

// Problem dimensions (fixed by the reference)
constexpr int B_  = 4;
constexpr int N_  = 4096;
constexpr int M_  = 1024;
constexpr int QD_ = 320;
constexpr int CD_ = 768;
constexpr int ID_ = 512;
constexpr int H_  = 8;
constexpr float SCALE_ = 0.125f;  // 64^-0.5

// Scratch (device globals; allocation inside kernel_launch is forbidden)
__device__ float g_q [(size_t)B_ * N_ * ID_];
__device__ float g_k [(size_t)B_ * M_ * ID_];
__device__ float g_v [(size_t)B_ * M_ * ID_];
__device__ float g_ao[(size_t)B_ * N_ * ID_];

// ---------------------------------------------------------------------------
// Helpers: bf16 packing / splitting, mma, ldmatrix, swizzled tile addressing
// ---------------------------------------------------------------------------
__device__ __forceinline__ uint32_t smem_u32(const void* p) {
    return (uint32_t)__cvta_generic_to_shared(p);
}
__device__ __forceinline__ uint32_t pk2(__nv_bfloat16 lo, __nv_bfloat16 hi) {
    return ((uint32_t)__bfloat16_as_ushort(hi) << 16) |
            (uint32_t)__bfloat16_as_ushort(lo);
}
// D += A * B  (m16n8k16, bf16 in, fp32 accum)
__device__ __forceinline__ void mma_bf16(float* d, const uint32_t* a, const uint32_t* b) {
    asm volatile(
        "mma.sync.aligned.m16n8k16.row.col.f32.bf16.bf16.f32 "
        "{%0,%1,%2,%3}, {%4,%5,%6,%7}, {%8,%9}, {%0,%1,%2,%3};\n"
        : "+f"(d[0]), "+f"(d[1]), "+f"(d[2]), "+f"(d[3])
        : "r"(a[0]), "r"(a[1]), "r"(a[2]), "r"(a[3]), "r"(b[0]), "r"(b[1]));
}
__device__ __forceinline__ void ldsm4(uint32_t* r, uint32_t a) {
    asm volatile("ldmatrix.sync.aligned.m8n8.x4.shared.b16 {%0,%1,%2,%3}, [%4];\n"
        : "=r"(r[0]), "=r"(r[1]), "=r"(r[2]), "=r"(r[3]) : "r"(a));
}
__device__ __forceinline__ void ldsm2(uint32_t* r, uint32_t a) {
    asm volatile("ldmatrix.sync.aligned.m8n8.x2.shared.b16 {%0,%1}, [%2];\n"
        : "=r"(r[0]), "=r"(r[1]) : "r"(a));
}
__device__ __forceinline__ void ldsm2t(uint32_t* r, uint32_t a) {
    asm volatile("ldmatrix.sync.aligned.m8n8.x2.trans.shared.b16 {%0,%1}, [%2];\n"
        : "=r"(r[0]), "=r"(r[1]) : "r"(a));
}
// Swizzled tile byte-address: row-major rows of `cpr` 16B-chunks; chunk XOR (row&7)
__device__ __forceinline__ uint32_t tile_addr(uint32_t base, int row, int cb, int cpr) {
    return base + (uint32_t)((row * cpr + (cb ^ (row & 7))) * 16);
}
// Split 8 consecutive fp32 into bf16 hi/lo chunks and store (swizzled)
__device__ __forceinline__ void store_split8(__nv_bfloat16* hi, __nv_bfloat16* lo,
                                             int row, int cb, int cpr, const float* f) {
    int off = (row * cpr + (cb ^ (row & 7))) * 8;
    uint32_t h[4], l[4];
    #pragma unroll
    for (int i = 0; i < 4; i++) {
        float x = f[2 * i], y = f[2 * i + 1];
        __nv_bfloat16 xh = __float2bfloat16_rn(x), yh = __float2bfloat16_rn(y);
        h[i] = pk2(xh, yh);
        l[i] = pk2(__float2bfloat16_rn(x - __bfloat162float(xh)),
                   __float2bfloat16_rn(y - __bfloat162float(yh)));
    }
    *reinterpret_cast<uint4*>(hi + off) = make_uint4(h[0], h[1], h[2], h[3]);
    *reinterpret_cast<uint4*>(lo + off) = make_uint4(l[0], l[1], l[2], l[3]);
}
__device__ __forceinline__ void split2(float x, float y, uint32_t& h, uint32_t& l) {
    __nv_bfloat16 xh = __float2bfloat16_rn(x), yh = __float2bfloat16_rn(y);
    h = pk2(xh, yh);
    l = pk2(__float2bfloat16_rn(x - __bfloat162float(xh)),
            __float2bfloat16_rn(y - __bfloat162float(yh)));
}

// ---------------------------------------------------------------------------
// GEMM (bf16x3 tensor core): C[M,N] = A[M,K] @ B[K,N] (+bias)
// Tile BM x BN x 64; warps laid out (BM/16) x (BN/64); each warp: 16 x 64.
// ---------------------------------------------------------------------------
template<int BM, int BN, bool BIAS>
__global__ void __launch_bounds__((BM/16)*(BN/64)*32) gemm_mma(
    const float* __restrict__ A, const float* __restrict__ Bm,
    const float* __restrict__ bias, float* __restrict__ C,
    int Mdim, int Ndim, int Kdim)
{
    constexpr int WR = BM / 16, WC = BN / 64, NT = WR * WC * 32;
    constexpr int BCH = BN / 8;                 // B chunks per row
    extern __shared__ __nv_bfloat16 sm[];
    __nv_bfloat16* Ahi = sm;
    __nv_bfloat16* Alo = Ahi + BM * 64;
    __nv_bfloat16* Bhi = Alo + BM * 64;
    __nv_bfloat16* Blo = Bhi + 64 * BN;

    const int tid = threadIdx.x, w = tid >> 5, lane = tid & 31;
    const int wr = w % WR, wc = w / WR;
    const int bm0 = blockIdx.y * BM, bn0 = blockIdx.x * BN;
    const int g = lane >> 2, t = lane & 3;

    float Cacc[8][4];
    #pragma unroll
    for (int i = 0; i < 8; i++)
        #pragma unroll
        for (int j = 0; j < 4; j++) Cacc[i][j] = 0.0f;

    const uint32_t ahi_b = smem_u32(Ahi), alo_b = smem_u32(Alo);
    const uint32_t bhi_b = smem_u32(Bhi), blo_b = smem_u32(Blo);

    for (int k0 = 0; k0 < Kdim; k0 += 64) {
        __syncthreads();
        for (int i = tid; i < BM * 8; i += NT) {
            int r = i >> 3, cb = i & 7;
            const float* src = A + (size_t)(bm0 + r) * Kdim + k0 + cb * 8;
            float f[8];
            float4 v0 = *(const float4*)src;
            float4 v1 = *(const float4*)(src + 4);
            f[0]=v0.x; f[1]=v0.y; f[2]=v0.z; f[3]=v0.w;
            f[4]=v1.x; f[5]=v1.y; f[6]=v1.z; f[7]=v1.w;
            store_split8(Ahi, Alo, r, cb, 8, f);
        }
        for (int i = tid; i < 64 * BCH; i += NT) {
            int r = i / BCH, cb = i % BCH;
            const float* src = Bm + (size_t)(k0 + r) * Ndim + bn0 + cb * 8;
            float f[8];
            float4 v0 = *(const float4*)src;
            float4 v1 = *(const float4*)(src + 4);
            f[0]=v0.x; f[1]=v0.y; f[2]=v0.z; f[3]=v0.w;
            f[4]=v1.x; f[5]=v1.y; f[6]=v1.z; f[7]=v1.w;
            store_split8(Bhi, Blo, r, cb, BCH, f);
        }
        __syncthreads();

        #pragma unroll
        for (int kc = 0; kc < 4; kc++) {
            uint32_t ah[4], al[4];
            int rowa = wr * 16 + (lane & 7) + ((lane >> 3) & 1) * 8;
            int cba = kc * 2 + (lane >> 4);
            ldsm4(ah, tile_addr(ahi_b, rowa, cba, 8));
            ldsm4(al, tile_addr(alo_b, rowa, cba, 8));
            #pragma unroll
            for (int db = 0; db < 8; db++) {
                uint32_t bh[2], bl[2];
                int rr = kc * 16 + (lane & 7) + ((lane >> 3) & 1) * 8;
                int cb = wc * 8 + db;
                ldsm2t(bh, tile_addr(bhi_b, rr, cb, BCH));
                ldsm2t(bl, tile_addr(blo_b, rr, cb, BCH));
                mma_bf16(Cacc[db], ah, bh);
                mma_bf16(Cacc[db], ah, bl);
                mma_bf16(Cacc[db], al, bh);
            }
        }
    }

    int r0 = bm0 + wr * 16 + g;
    #pragma unroll
    for (int db = 0; db < 8; db++) {
        int c = bn0 + wc * 64 + db * 8 + 2 * t;
        float b0 = BIAS ? bias[c] : 0.0f;
        float b1 = BIAS ? bias[c + 1] : 0.0f;
        float2 r;
        r.x = Cacc[db][0] + b0; r.y = Cacc[db][1] + b1;
        *(float2*)(C + (size_t)r0 * Ndim + c) = r;
        r.x = Cacc[db][2] + b0; r.y = Cacc[db][3] + b1;
        *(float2*)(C + (size_t)(r0 + 8) * Ndim + c) = r;
    }
}

// ---------------------------------------------------------------------------
// Flash attention (bf16x3 tensor core). Block = 64 queries of one (b,h);
// 4 warps x 16 rows. S accum fragments feed PV A fragments directly.
// ---------------------------------------------------------------------------
constexpr int FLASH_SMEM = 6 * 64 * 64 * 2;   // Qhi/Qlo/Khi/Klo/Vhi/Vlo = 49152 B

__global__ void __launch_bounds__(128) flash_mma(
    const float* __restrict__ Q, const float* __restrict__ K,
    const float* __restrict__ V, float* __restrict__ O)
{
    extern __shared__ __nv_bfloat16 sm[];
    __nv_bfloat16* Qhi = sm;
    __nv_bfloat16* Qlo = sm + 4096;
    __nv_bfloat16* Khi = sm + 8192;
    __nv_bfloat16* Klo = sm + 12288;
    __nv_bfloat16* Vhi = sm + 16384;
    __nv_bfloat16* Vlo = sm + 20480;

    const int tid = threadIdx.x, w = tid >> 5, lane = tid & 31;
    const int n0 = blockIdx.x * 64, h = blockIdx.y, b = blockIdx.z;
    const int g = lane >> 2, t = lane & 3;

    // Load + split Q tile (scale folded in; x0.125 is exact)
    const float* qb = Q + ((size_t)(b * N_ + n0)) * ID_ + h * 64;
    for (int i = tid; i < 512; i += 128) {
        int r = i >> 3, cb = i & 7;
        const float* src = qb + (size_t)r * ID_ + cb * 8;
        float f[8];
        float4 v0 = *(const float4*)src;
        float4 v1 = *(const float4*)(src + 4);
        f[0]=v0.x*SCALE_; f[1]=v0.y*SCALE_; f[2]=v0.z*SCALE_; f[3]=v0.w*SCALE_;
        f[4]=v1.x*SCALE_; f[5]=v1.y*SCALE_; f[6]=v1.z*SCALE_; f[7]=v1.w*SCALE_;
        store_split8(Qhi, Qlo, r, cb, 8, f);
    }
    __syncthreads();

    // Preload Q fragments (16 rows per warp, all 4 k-chunks, hi+lo)
    uint32_t qh[4][4], ql[4][4];
    {
        const uint32_t qhi_b = smem_u32(Qhi), qlo_b = smem_u32(Qlo);
        int rowa = w * 16 + (lane & 7) + ((lane >> 3) & 1) * 8;
        #pragma unroll
        for (int kc = 0; kc < 4; kc++) {
            int cba = kc * 2 + (lane >> 4);
            ldsm4(qh[kc], tile_addr(qhi_b, rowa, cba, 8));
            ldsm4(ql[kc], tile_addr(qlo_b, rowa, cba, 8));
        }
    }

    float m0 = -1e30f, m1 = -1e30f, l0 = 0.0f, l1 = 0.0f;
    float Oa[8][4];
    #pragma unroll
    for (int i = 0; i < 8; i++)
        #pragma unroll
        for (int j = 0; j < 4; j++) Oa[i][j] = 0.0f;

    const float* kb = K + ((size_t)(b * M_)) * ID_ + h * 64;
    const float* vb = V + ((size_t)(b * M_)) * ID_ + h * 64;
    const uint32_t khi_b = smem_u32(Khi), klo_b = smem_u32(Klo);
    const uint32_t vhi_b = smem_u32(Vhi), vlo_b = smem_u32(Vlo);

    for (int kt = 0; kt < M_ / 64; kt++) {
        __syncthreads();
        // Load + split K and V tiles
        for (int i = tid; i < 1024; i += 128) {
            int r = (i >> 3) & 63, cb = i & 7, isv = i >> 9;
            const float* src = (isv ? vb : kb) + (size_t)(kt * 64 + r) * ID_ + cb * 8;
            float f[8];
            float4 v0 = *(const float4*)src;
            float4 v1 = *(const float4*)(src + 4);
            f[0]=v0.x; f[1]=v0.y; f[2]=v0.z; f[3]=v0.w;
            f[4]=v1.x; f[5]=v1.y; f[6]=v1.z; f[7]=v1.w;
            store_split8(isv ? Vhi : Khi, isv ? Vlo : Klo, r, cb, 8, f);
        }
        __syncthreads();

        // S = Q @ K^T  (bf16x3)
        float S[8][4];
        #pragma unroll
        for (int i = 0; i < 8; i++)
            #pragma unroll
            for (int j = 0; j < 4; j++) S[i][j] = 0.0f;

        #pragma unroll
        for (int kc = 0; kc < 4; kc++) {
            #pragma unroll
            for (int nb = 0; nb < 8; nb++) {
                uint32_t bh[2], bl[2];
                int rr = nb * 8 + (lane & 7);
                int cb = kc * 2 + ((lane >> 3) & 1);
                ldsm2(bh, tile_addr(khi_b, rr, cb, 8));
                ldsm2(bl, tile_addr(klo_b, rr, cb, 8));
                mma_bf16(S[nb], qh[kc], bh);
                mma_bf16(S[nb], qh[kc], bl);
                mma_bf16(S[nb], ql[kc], bh);
            }
        }

        // Online softmax (rows g and g+8 of this warp's 16)
        float vx0 = -1e30f, vx1 = -1e30f;
        #pragma unroll
        for (int nb = 0; nb < 8; nb++) {
            vx0 = fmaxf(vx0, fmaxf(S[nb][0], S[nb][1]));
            vx1 = fmaxf(vx1, fmaxf(S[nb][2], S[nb][3]));
        }
        vx0 = fmaxf(vx0, __shfl_xor_sync(0xffffffffu, vx0, 1, 4));
        vx0 = fmaxf(vx0, __shfl_xor_sync(0xffffffffu, vx0, 2, 4));
        vx1 = fmaxf(vx1, __shfl_xor_sync(0xffffffffu, vx1, 1, 4));
        vx1 = fmaxf(vx1, __shfl_xor_sync(0xffffffffu, vx1, 2, 4));
        float mn0 = fmaxf(m0, vx0), mn1 = fmaxf(m1, vx1);
        float a0 = __expf(m0 - mn0), a1 = __expf(m1 - mn1);
        float rs0 = 0.0f, rs1 = 0.0f;
        #pragma unroll
        for (int nb = 0; nb < 8; nb++) {
            S[nb][0] = __expf(S[nb][0] - mn0);
            S[nb][1] = __expf(S[nb][1] - mn0);
            S[nb][2] = __expf(S[nb][2] - mn1);
            S[nb][3] = __expf(S[nb][3] - mn1);
            rs0 += S[nb][0] + S[nb][1];
            rs1 += S[nb][2] + S[nb][3];
        }
        rs0 += __shfl_xor_sync(0xffffffffu, rs0, 1, 4);
        rs0 += __shfl_xor_sync(0xffffffffu, rs0, 2, 4);
        rs1 += __shfl_xor_sync(0xffffffffu, rs1, 1, 4);
        rs1 += __shfl_xor_sync(0xffffffffu, rs1, 2, 4);
        l0 = l0 * a0 + rs0; l1 = l1 * a1 + rs1;
        m0 = mn0; m1 = mn1;
        #pragma unroll
        for (int db = 0; db < 8; db++) {
            Oa[db][0] *= a0; Oa[db][1] *= a0;
            Oa[db][2] *= a1; Oa[db][3] *= a1;
        }

        // O += P @ V  (P = S fragments, split to bf16 hi/lo A-fragments)
        #pragma unroll
        for (int kc = 0; kc < 4; kc++) {
            uint32_t ah[4], al[4];
            split2(S[2*kc  ][0], S[2*kc  ][1], ah[0], al[0]);
            split2(S[2*kc  ][2], S[2*kc  ][3], ah[1], al[1]);
            split2(S[2*kc+1][0], S[2*kc+1][1], ah[2], al[2]);
            split2(S[2*kc+1][2], S[2*kc+1][3], ah[3], al[3]);
            int rr = kc * 16 + (lane & 7) + ((lane >> 3) & 1) * 8;
            #pragma unroll
            for (int db = 0; db < 8; db++) {
                uint32_t vh[2], vl[2];
                ldsm2t(vh, tile_addr(vhi_b, rr, db, 8));
                ldsm2t(vl, tile_addr(vlo_b, rr, db, 8));
                mma_bf16(Oa[db], ah, vh);
                mma_bf16(Oa[db], ah, vl);
                mma_bf16(Oa[db], al, vh);
            }
        }
    }

    // Normalize + store
    float i0 = 1.0f / l0, i1 = 1.0f / l1;
    float* ob = O + ((size_t)(b * N_ + n0)) * ID_ + h * 64;
    int r0 = w * 16 + g;
    #pragma unroll
    for (int db = 0; db < 8; db++) {
        int c = db * 8 + 2 * t;
        float2 r;
        r.x = Oa[db][0] * i0; r.y = Oa[db][1] * i0;
        *(float2*)(ob + (size_t)r0 * ID_ + c) = r;
        r.x = Oa[db][2] * i1; r.y = Oa[db][3] * i1;
        *(float2*)(ob + (size_t)(r0 + 8) * ID_ + c) = r;
    }
}

// ---------------------------------------------------------------------------
// Launch
// ---------------------------------------------------------------------------
extern "C" void kernel_launch(void* const* d_in, const int* in_sizes, int n_in,
                              void* d_out, int out_size)
{
    const float* x   = (const float*)d_in[0];
    const float* ctx = (const float*)d_in[1];
    const float* Wq  = (const float*)d_in[2];
    const float* Wk  = (const float*)d_in[3];
    const float* Wv  = (const float*)d_in[4];
    const float* Wo  = (const float*)d_in[5];
    const float* bo  = (const float*)d_in[6];
    float* out = (float*)d_out;

    void *pq, *pk, *pv, *pao;
    cudaGetSymbolAddress(&pq,  g_q);
    cudaGetSymbolAddress(&pk,  g_k);
    cudaGetSymbolAddress(&pv,  g_v);
    cudaGetSymbolAddress(&pao, g_ao);
    float* q  = (float*)pq;
    float* k  = (float*)pk;
    float* v  = (float*)pv;
    float* ao = (float*)pao;

    constexpr int GEMM_SMEM = 6 * 64 * 64 * 2 * 2;  // (BM*64 + 64*BN)*2 tiles *2B = 49152
    cudaFuncSetAttribute(gemm_mma<64, 128, false>,
                         cudaFuncAttributeMaxDynamicSharedMemorySize, GEMM_SMEM);
    cudaFuncSetAttribute(gemm_mma<128, 64, true>,
                         cudaFuncAttributeMaxDynamicSharedMemorySize, GEMM_SMEM);
    cudaFuncSetAttribute(flash_mma,
                         cudaFuncAttributeMaxDynamicSharedMemorySize, FLASH_SMEM);

    // q = x @ Wq : [16384,320] x [320,512]
    gemm_mma<64, 128, false><<<dim3(ID_ / 128, (B_ * N_) / 64), 256, GEMM_SMEM>>>(
        x, Wq, nullptr, q, B_ * N_, ID_, QD_);
    // k = ctx @ Wk : [4096,768] x [768,512]
    gemm_mma<64, 128, false><<<dim3(ID_ / 128, (B_ * M_) / 64), 256, GEMM_SMEM>>>(
        ctx, Wk, nullptr, k, B_ * M_, ID_, CD_);
    // v = ctx @ Wv
    gemm_mma<64, 128, false><<<dim3(ID_ / 128, (B_ * M_) / 64), 256, GEMM_SMEM>>>(
        ctx, Wv, nullptr, v, B_ * M_, ID_, CD_);
    // attention
    flash_mma<<<dim3(N_ / 64, H_, B_), 128, FLASH_SMEM>>>(q, k, v, ao);
    // out = ao @ Wo + bo : [16384,512] x [512,320]
    gemm_mma<128, 64, true><<<dim3(QD_ / 64, (B_ * N_) / 128), 256, GEMM_SMEM>>>(
        ao, Wo, bo, out, B_ * N_, QD_, ID_);
}

// round 7
// speedup vs baseline: 3.3040x; 1.4622x over previous
#include <cuda_runtime.h>
#include <cuda_bf16.h>
#include <cstdint>

using bf16 = __nv_bfloat16;

constexpr int B_  = 4;
constexpr int N_  = 4096;
constexpr int M_  = 1024;
constexpr int QD_ = 320;
constexpr int CD_ = 768;
constexpr int ID_ = 512;
constexpr int H_  = 8;
constexpr float SCALE_ = 0.125f;

// ---------------------------------------------------------------------------
// Device-global scratch (hi/lo bf16 pairs)
// ---------------------------------------------------------------------------
__device__ bf16 g_xhi[16384 * 320], g_xlo[16384 * 320];
__device__ bf16 g_chi[4096 * 768],  g_clo[4096 * 768];
__device__ bf16 g_wqhi[320 * 512],  g_wqlo[320 * 512];
__device__ bf16 g_wkhi[768 * 512],  g_wklo[768 * 512];
__device__ bf16 g_wvhi[768 * 512],  g_wvlo[768 * 512];
__device__ bf16 g_wohi[512 * 320],  g_wolo[512 * 320];
__device__ bf16 g_qhi[16384 * 512], g_qlo[16384 * 512];   // head-major [b,h,n,64]
__device__ bf16 g_khi[4096 * 512],  g_klo[4096 * 512];    // head-major [b,h,m,64]
__device__ bf16 g_vhi[4096 * 512],  g_vlo[4096 * 512];
__device__ bf16 g_ohi[16384 * 512], g_olo[16384 * 512];   // row-major [b*n, 512]

// ---------------------------------------------------------------------------
// Helpers
// ---------------------------------------------------------------------------
__device__ __forceinline__ uint32_t smem_u32(const void* p) {
    return (uint32_t)__cvta_generic_to_shared(p);
}
__device__ __forceinline__ uint32_t pk2(bf16 lo, bf16 hi) {
    return ((uint32_t)__bfloat16_as_ushort(hi) << 16) |
            (uint32_t)__bfloat16_as_ushort(lo);
}
__device__ __forceinline__ void split2(float x, float y, uint32_t& h, uint32_t& l) {
    bf16 xh = __float2bfloat16_rn(x), yh = __float2bfloat16_rn(y);
    h = pk2(xh, yh);
    l = pk2(__float2bfloat16_rn(x - __bfloat162float(xh)),
            __float2bfloat16_rn(y - __bfloat162float(yh)));
}
__device__ __forceinline__ void mma_bf16(float* d, const uint32_t* a, const uint32_t* b) {
    asm volatile(
        "mma.sync.aligned.m16n8k16.row.col.f32.bf16.bf16.f32 "
        "{%0,%1,%2,%3}, {%4,%5,%6,%7}, {%8,%9}, {%0,%1,%2,%3};\n"
        : "+f"(d[0]), "+f"(d[1]), "+f"(d[2]), "+f"(d[3])
        : "r"(a[0]), "r"(a[1]), "r"(a[2]), "r"(a[3]), "r"(b[0]), "r"(b[1]));
}
__device__ __forceinline__ void ldsm4(uint32_t* r, uint32_t a) {
    asm volatile("ldmatrix.sync.aligned.m8n8.x4.shared.b16 {%0,%1,%2,%3}, [%4];\n"
        : "=r"(r[0]), "=r"(r[1]), "=r"(r[2]), "=r"(r[3]) : "r"(a));
}
__device__ __forceinline__ void ldsm4t(uint32_t* r, uint32_t a) {
    asm volatile("ldmatrix.sync.aligned.m8n8.x4.trans.shared.b16 {%0,%1,%2,%3}, [%4];\n"
        : "=r"(r[0]), "=r"(r[1]), "=r"(r[2]), "=r"(r[3]) : "r"(a));
}
// byte address of 16B chunk (row, cb) in a swizzled tile with cpr chunks/row
__device__ __forceinline__ uint32_t tile_addr(uint32_t base, int row, int cb, int cpr) {
    return base + (uint32_t)((row * cpr + (cb ^ (row & 7))) * 16);
}
__device__ __forceinline__ void cp_async16(uint32_t dst, const void* src) {
    asm volatile("cp.async.ca.shared.global [%0], [%1], 16;\n" :: "r"(dst), "l"(src));
}
__device__ __forceinline__ void cp_commit() {
    asm volatile("cp.async.commit_group;\n");
}
template<int NW> __device__ __forceinline__ void cp_wait() {
    asm volatile("cp.async.wait_group %0;\n" :: "n"(NW));
}

// ---------------------------------------------------------------------------
// Split fp32 -> bf16 hi/lo
// ---------------------------------------------------------------------------
__global__ void split_kernel(const float4* __restrict__ src,
                             uint2* __restrict__ hi, uint2* __restrict__ lo, int n4)
{
    int i = blockIdx.x * blockDim.x + threadIdx.x;
    if (i >= n4) return;
    float4 v = src[i];
    uint32_t h0, l0, h1, l1;
    split2(v.x, v.y, h0, l0);
    split2(v.z, v.w, h1, l1);
    hi[i] = make_uint2(h0, h1);
    lo[i] = make_uint2(l0, l1);
}

// ---------------------------------------------------------------------------
// bf16x3 GEMM, pre-split operands, cp.async double-buffered, BK=64.
// Warp tile 32x64. EPI=0: fp32 C + bias. EPI=1: split to head-major hi/lo.
// ---------------------------------------------------------------------------
template<int BM, int BN, int EPI>
__global__ void __launch_bounds__((BM/32)*(BN/64)*32) gemm_bf3(
    const bf16* __restrict__ Ahi, const bf16* __restrict__ Alo,
    const bf16* __restrict__ Bhi, const bf16* __restrict__ Blo,
    const float* __restrict__ bias, float* __restrict__ Cf,
    bf16* __restrict__ Ohi, bf16* __restrict__ Olo,
    int Ndim, int Kdim, int seq, float scale)
{
    constexpr int WR = BM / 32, WC = BN / 64, NT = WR * WC * 32;
    constexpr int BCH = BN / 8;
    constexpr int ABUF = BM * 64;          // elements (one of hi/lo)
    constexpr int BBUF = 64 * BN;
    constexpr int BUFSZ = 2 * ABUF + 2 * BBUF;

    extern __shared__ bf16 smem[];
    const int tid = threadIdx.x, w = tid >> 5, lane = tid & 31;
    const int wr = w % WR, wc = w / WR;
    const int bm0 = blockIdx.y * BM, bn0 = blockIdx.x * BN;
    const int g = lane >> 2, t = lane & 3;
    const uint32_t sbase = smem_u32(smem);

    float acc[2][8][4];
    #pragma unroll
    for (int a = 0; a < 2; a++)
        #pragma unroll
        for (int i = 0; i < 8; i++)
            #pragma unroll
            for (int j = 0; j < 4; j++) acc[a][i][j] = 0.0f;

    auto issue = [&](int k0, int stage) {
        uint32_t sb = sbase + (uint32_t)(stage * BUFSZ * 2);
        for (int i = tid; i < BM * 8 * 2; i += NT) {
            int half = i >= BM * 8;
            int rem = i - half * BM * 8;
            int r = rem >> 3, cb = rem & 7;
            const bf16* src = (half ? Alo : Ahi) + (size_t)(bm0 + r) * Kdim + k0 + cb * 8;
            uint32_t dst = sb + (uint32_t)(half * ABUF * 2) +
                           (uint32_t)((r * 8 + (cb ^ (r & 7))) * 16);
            cp_async16(dst, src);
        }
        for (int i = tid; i < 64 * BCH * 2; i += NT) {
            int half = i >= 64 * BCH;
            int rem = i - half * 64 * BCH;
            int r = rem / BCH, cb = rem - r * BCH;
            const bf16* src = (half ? Blo : Bhi) + (size_t)(k0 + r) * Ndim + bn0 + cb * 8;
            uint32_t dst = sb + (uint32_t)((2 * ABUF + half * BBUF) * 2) +
                           (uint32_t)((r * BCH + (cb ^ (r & 7))) * 16);
            cp_async16(dst, src);
        }
    };

    const int KT = Kdim / 64;
    issue(0, 0); cp_commit();

    for (int kt = 0; kt < KT; kt++) {
        int cur = kt & 1;
        if (kt + 1 < KT) { issue((kt + 1) * 64, cur ^ 1); cp_commit(); cp_wait<1>(); }
        else             { cp_wait<0>(); }
        __syncthreads();

        uint32_t ah_b = sbase + (uint32_t)(cur * BUFSZ * 2);
        uint32_t al_b = ah_b + ABUF * 2;
        uint32_t bh_b = ah_b + 2 * ABUF * 2;
        uint32_t bl_b = bh_b + BBUF * 2;

        #pragma unroll
        for (int kc = 0; kc < 4; kc++) {
            uint32_t Af[2][2][4];
            #pragma unroll
            for (int rb = 0; rb < 2; rb++) {
                int rowa = wr * 32 + rb * 16 + (lane & 7) + ((lane >> 3) & 1) * 8;
                int cba = kc * 2 + (lane >> 4);
                ldsm4(Af[rb][0], tile_addr(ah_b, rowa, cba, 8));
                ldsm4(Af[rb][1], tile_addr(al_b, rowa, cba, 8));
            }
            #pragma unroll
            for (int dbp = 0; dbp < 4; dbp++) {
                int db = wc * 8 + dbp * 2;
                int rowb = kc * 16 + ((lane >> 3) & 1) * 8 + (lane & 7);
                int cbb = db + (lane >> 4);
                uint32_t bh[4], bl[4];
                ldsm4t(bh, tile_addr(bh_b, rowb, cbb, BCH));
                ldsm4t(bl, tile_addr(bl_b, rowb, cbb, BCH));
                #pragma unroll
                for (int rb = 0; rb < 2; rb++) {
                    #pragma unroll
                    for (int j = 0; j < 2; j++) {
                        float* d = acc[rb][dbp * 2 + j];
                        mma_bf16(d, Af[rb][0], bh + 2 * j);
                        mma_bf16(d, Af[rb][0], bl + 2 * j);
                        mma_bf16(d, Af[rb][1], bh + 2 * j);
                    }
                }
            }
        }
        __syncthreads();
    }

    // Epilogue
    #pragma unroll
    for (int rb = 0; rb < 2; rb++) {
        int row0 = bm0 + wr * 32 + rb * 16 + g;
        if (EPI == 0) {
            #pragma unroll
            for (int db = 0; db < 8; db++) {
                int c = bn0 + wc * 64 + db * 8 + 2 * t;
                float b0 = bias[c], b1 = bias[c + 1];
                float2 r;
                r.x = acc[rb][db][0] + b0; r.y = acc[rb][db][1] + b1;
                *(float2*)(Cf + (size_t)row0 * Ndim + c) = r;
                r.x = acc[rb][db][2] + b0; r.y = acc[rb][db][3] + b1;
                *(float2*)(Cf + (size_t)(row0 + 8) * Ndim + c) = r;
            }
        } else {
            int b0i = row0 / seq, s0 = row0 - b0i * seq;
            int b1i = (row0 + 8) / seq, s1 = (row0 + 8) - b1i * seq;
            #pragma unroll
            for (int db = 0; db < 8; db++) {
                int c = bn0 + wc * 64 + db * 8 + 2 * t;
                int h = c >> 6, d = c & 63;
                uint32_t hh, ll;
                size_t o0 = ((size_t)(b0i * H_ + h) * seq + s0) * 64 + d;
                split2(acc[rb][db][0] * scale, acc[rb][db][1] * scale, hh, ll);
                *(uint32_t*)(Ohi + o0) = hh;
                *(uint32_t*)(Olo + o0) = ll;
                size_t o1 = ((size_t)(b1i * H_ + h) * seq + s1) * 64 + d;
                split2(acc[rb][db][2] * scale, acc[rb][db][3] * scale, hh, ll);
                *(uint32_t*)(Ohi + o1) = hh;
                *(uint32_t*)(Olo + o1) = ll;
            }
        }
    }
}

// ---------------------------------------------------------------------------
// Flash attention: 128 queries/CTA, 8 warps, pre-split bf16 inputs,
// cp.async double-buffered K/V. Q is pre-scaled by SCALE_ (folded into the
// q-projection epilogue) — no additional scaling here.
// ---------------------------------------------------------------------------
constexpr int FLASH_SMEM = (16384 + 32768) * 2;   // 96 KB

__global__ void __launch_bounds__(256, 2) flash_bf3(
    const bf16* __restrict__ Qhi_g, const bf16* __restrict__ Qlo_g,
    const bf16* __restrict__ Khi_g, const bf16* __restrict__ Klo_g,
    const bf16* __restrict__ Vhi_g, const bf16* __restrict__ Vlo_g,
    bf16* __restrict__ Ohi_g, bf16* __restrict__ Olo_g)
{
    extern __shared__ bf16 smem[];
    const int tid = threadIdx.x, w = tid >> 5, lane = tid & 31;
    const int n0 = blockIdx.x * 128, h = blockIdx.y, b = blockIdx.z;
    const int g = lane >> 2, t = lane & 3;
    const uint32_t sbase = smem_u32(smem);
    const uint32_t ql_b = sbase + 8192 * 2;

    const size_t qoff = ((size_t)(b * H_ + h) * N_ + n0) * 64;
    const size_t koff = ((size_t)(b * H_ + h) * M_) * 64;

    auto issueKV = [&](int kt, int stage) {
        uint32_t sb = sbase + (uint32_t)((16384 + stage * 16384) * 2);
        const bf16* srcs[4] = {Khi_g + koff, Klo_g + koff, Vhi_g + koff, Vlo_g + koff};
        #pragma unroll
        for (int j = 0; j < 8; j++) {
            int i = tid + j * 256;
            int arr = i >> 9, rem = i & 511, r = rem >> 3, cb = rem & 7;
            const bf16* src = srcs[arr] + (size_t)(kt * 64 + r) * 64 + cb * 8;
            uint32_t dst = sb + (uint32_t)(arr * 4096 * 2) +
                           (uint32_t)((r * 8 + (cb ^ (r & 7))) * 16);
            cp_async16(dst, src);
        }
    };

    issueKV(0, 0); cp_commit();

    // Q tiles -> smem (swizzled)
    for (int i = tid; i < 2048; i += 256) {
        int half = i >> 10, rem = i & 1023, r = rem >> 3, cb = rem & 7;
        const bf16* src = (half ? Qlo_g : Qhi_g) + qoff + (size_t)r * 64 + cb * 8;
        uint4 v = *(const uint4*)src;
        *(uint4*)(smem + (half ? 8192 : 0) + (r * 8 + (cb ^ (r & 7))) * 8) = v;
    }
    __syncthreads();

    const int rowa = w * 16 + (lane & 7) + ((lane >> 3) & 1) * 8;
    uint32_t qh[4][4];
    #pragma unroll
    for (int kc = 0; kc < 4; kc++)
        ldsm4(qh[kc], tile_addr(sbase, rowa, kc * 2 + (lane >> 4), 8));

    float m0 = -1e30f, m1 = -1e30f, l0 = 0.0f, l1 = 0.0f;
    float Oa[8][4];
    #pragma unroll
    for (int i = 0; i < 8; i++)
        #pragma unroll
        for (int j = 0; j < 4; j++) Oa[i][j] = 0.0f;

    for (int kt = 0; kt < M_ / 64; kt++) {
        int cur = kt & 1;
        if (kt + 1 < M_ / 64) { issueKV(kt + 1, cur ^ 1); cp_commit(); cp_wait<1>(); }
        else                  { cp_wait<0>(); }
        __syncthreads();

        uint32_t kh_b = sbase + (uint32_t)((16384 + cur * 16384) * 2);
        uint32_t kl_b = kh_b + 4096 * 2;
        uint32_t vh_b = kh_b + 8192 * 2;
        uint32_t vl_b = kh_b + 12288 * 2;

        // S = Q @ K^T (bf16x3); Q already carries the softmax scale
        float S[8][4];
        #pragma unroll
        for (int i = 0; i < 8; i++)
            #pragma unroll
            for (int j = 0; j < 4; j++) S[i][j] = 0.0f;

        const int rowk = ((lane >> 4)) * 8 + (lane & 7);   // + nbp*16
        const int cbk0 = (lane >> 3) & 1;                  // + kc*2
        #pragma unroll
        for (int kc = 0; kc < 4; kc++) {
            uint32_t ql[4];
            ldsm4(ql, tile_addr(ql_b, rowa, kc * 2 + (lane >> 4), 8));
            #pragma unroll
            for (int nbp = 0; nbp < 4; nbp++) {
                uint32_t bh[4], bl[4];
                int rr = nbp * 16 + rowk;
                int cb = kc * 2 + cbk0;
                ldsm4(bh, tile_addr(kh_b, rr, cb, 8));
                ldsm4(bl, tile_addr(kl_b, rr, cb, 8));
                #pragma unroll
                for (int j = 0; j < 2; j++) {
                    float* d = S[nbp * 2 + j];
                    mma_bf16(d, qh[kc], bh + 2 * j);
                    mma_bf16(d, qh[kc], bl + 2 * j);
                    mma_bf16(d, ql,     bh + 2 * j);
                }
            }
        }

        // Online softmax
        float vx0 = -1e30f, vx1 = -1e30f;
        #pragma unroll
        for (int nb = 0; nb < 8; nb++) {
            vx0 = fmaxf(vx0, fmaxf(S[nb][0], S[nb][1]));
            vx1 = fmaxf(vx1, fmaxf(S[nb][2], S[nb][3]));
        }
        vx0 = fmaxf(vx0, __shfl_xor_sync(0xffffffffu, vx0, 1, 4));
        vx0 = fmaxf(vx0, __shfl_xor_sync(0xffffffffu, vx0, 2, 4));
        vx1 = fmaxf(vx1, __shfl_xor_sync(0xffffffffu, vx1, 1, 4));
        vx1 = fmaxf(vx1, __shfl_xor_sync(0xffffffffu, vx1, 2, 4));
        float mn0 = fmaxf(m0, vx0), mn1 = fmaxf(m1, vx1);
        float a0 = __expf(m0 - mn0), a1 = __expf(m1 - mn1);
        float rs0 = 0.0f, rs1 = 0.0f;
        #pragma unroll
        for (int nb = 0; nb < 8; nb++) {
            S[nb][0] = __expf(S[nb][0] - mn0);
            S[nb][1] = __expf(S[nb][1] - mn0);
            S[nb][2] = __expf(S[nb][2] - mn1);
            S[nb][3] = __expf(S[nb][3] - mn1);
            rs0 += S[nb][0] + S[nb][1];
            rs1 += S[nb][2] + S[nb][3];
        }
        rs0 += __shfl_xor_sync(0xffffffffu, rs0, 1, 4);
        rs0 += __shfl_xor_sync(0xffffffffu, rs0, 2, 4);
        rs1 += __shfl_xor_sync(0xffffffffu, rs1, 1, 4);
        rs1 += __shfl_xor_sync(0xffffffffu, rs1, 2, 4);
        l0 = l0 * a0 + rs0; l1 = l1 * a1 + rs1;
        m0 = mn0; m1 = mn1;
        #pragma unroll
        for (int db = 0; db < 8; db++) {
            Oa[db][0] *= a0; Oa[db][1] *= a0;
            Oa[db][2] *= a1; Oa[db][3] *= a1;
        }

        // O += P @ V
        #pragma unroll
        for (int kc = 0; kc < 4; kc++) {
            uint32_t ah[4], al[4];
            split2(S[2*kc  ][0], S[2*kc  ][1], ah[0], al[0]);
            split2(S[2*kc  ][2], S[2*kc  ][3], ah[1], al[1]);
            split2(S[2*kc+1][0], S[2*kc+1][1], ah[2], al[2]);
            split2(S[2*kc+1][2], S[2*kc+1][3], ah[3], al[3]);
            int rowv = kc * 16 + ((lane >> 3) & 1) * 8 + (lane & 7);
            #pragma unroll
            for (int dbp = 0; dbp < 4; dbp++) {
                int cbv = dbp * 2 + (lane >> 4);
                uint32_t vh[4], vl[4];
                ldsm4t(vh, tile_addr(vh_b, rowv, cbv, 8));
                ldsm4t(vl, tile_addr(vl_b, rowv, cbv, 8));
                #pragma unroll
                for (int j = 0; j < 2; j++) {
                    float* d = Oa[dbp * 2 + j];
                    mma_bf16(d, ah, vh + 2 * j);
                    mma_bf16(d, ah, vl + 2 * j);
                    mma_bf16(d, al, vh + 2 * j);
                }
            }
        }
        __syncthreads();
    }

    // Epilogue: normalize, split to hi/lo, store row-major [b*N+n, 512]
    float i0 = 1.0f / l0, i1 = 1.0f / l1;
    int rq = w * 16 + g;
    #pragma unroll
    for (int db = 0; db < 8; db++) {
        int c = h * 64 + db * 8 + 2 * t;
        uint32_t hh, ll;
        size_t o0 = (size_t)(b * N_ + n0 + rq) * 512 + c;
        split2(Oa[db][0] * i0, Oa[db][1] * i0, hh, ll);
        *(uint32_t*)(g_ohi + o0) = hh;
        *(uint32_t*)(g_olo + o0) = ll;
        size_t o1 = (size_t)(b * N_ + n0 + rq + 8) * 512 + c;
        split2(Oa[db][2] * i1, Oa[db][3] * i1, hh, ll);
        *(uint32_t*)(g_ohi + o1) = hh;
        *(uint32_t*)(g_olo + o1) = ll;
    }
}

// ---------------------------------------------------------------------------
// Launch
// ---------------------------------------------------------------------------
extern "C" void kernel_launch(void* const* d_in, const int* in_sizes, int n_in,
                              void* d_out, int out_size)
{
    const float* x   = (const float*)d_in[0];
    const float* ctx = (const float*)d_in[1];
    const float* Wq  = (const float*)d_in[2];
    const float* Wk  = (const float*)d_in[3];
    const float* Wv  = (const float*)d_in[4];
    const float* Wo  = (const float*)d_in[5];
    const float* bo  = (const float*)d_in[6];
    float* out = (float*)d_out;

    #define SYM(p, s) void* p; cudaGetSymbolAddress(&p, s);
    SYM(xhi, g_xhi) SYM(xlo, g_xlo) SYM(chi, g_chi) SYM(clo, g_clo)
    SYM(wqhi, g_wqhi) SYM(wqlo, g_wqlo) SYM(wkhi, g_wkhi) SYM(wklo, g_wklo)
    SYM(wvhi, g_wvhi) SYM(wvlo, g_wvlo) SYM(wohi, g_wohi) SYM(wolo, g_wolo)
    SYM(qhi, g_qhi) SYM(qlo, g_qlo) SYM(khi, g_khi) SYM(klo, g_klo)
    SYM(vhi, g_vhi) SYM(vlo, g_vlo) SYM(ohi, g_ohi) SYM(olo, g_olo)
    #undef SYM

    constexpr int GEMM_SMEM = (2 * 64 * 64 + 2 * 64 * 128) * 2 * 2;  // 96 KB
    cudaFuncSetAttribute(gemm_bf3<64, 128, 1>,
                         cudaFuncAttributeMaxDynamicSharedMemorySize, GEMM_SMEM);
    cudaFuncSetAttribute(gemm_bf3<128, 64, 0>,
                         cudaFuncAttributeMaxDynamicSharedMemorySize, GEMM_SMEM);
    cudaFuncSetAttribute(flash_bf3,
                         cudaFuncAttributeMaxDynamicSharedMemorySize, FLASH_SMEM);

    auto split = [](const void* s, void* h, void* l, int n) {
        split_kernel<<<(n / 4 + 255) / 256, 256>>>(
            (const float4*)s, (uint2*)h, (uint2*)l, n / 4);
    };
    split(x,   xhi,  xlo,  16384 * 320);
    split(ctx, chi,  clo,  4096 * 768);
    split(Wq,  wqhi, wqlo, 320 * 512);
    split(Wk,  wkhi, wklo, 768 * 512);
    split(Wv,  wvhi, wvlo, 768 * 512);
    split(Wo,  wohi, wolo, 512 * 320);

    // Projections (write head-major split q/k/v; q gets SCALE_ folded in ONCE here)
    gemm_bf3<64, 128, 1><<<dim3(4, 256), 128, GEMM_SMEM>>>(
        (const bf16*)xhi, (const bf16*)xlo, (const bf16*)wqhi, (const bf16*)wqlo,
        nullptr, nullptr, (bf16*)qhi, (bf16*)qlo, 512, 320, N_, SCALE_);
    gemm_bf3<64, 128, 1><<<dim3(4, 64), 128, GEMM_SMEM>>>(
        (const bf16*)chi, (const bf16*)clo, (const bf16*)wkhi, (const bf16*)wklo,
        nullptr, nullptr, (bf16*)khi, (bf16*)klo, 512, 768, M_, 1.0f);
    gemm_bf3<64, 128, 1><<<dim3(4, 64), 128, GEMM_SMEM>>>(
        (const bf16*)chi, (const bf16*)clo, (const bf16*)wvhi, (const bf16*)wvlo,
        nullptr, nullptr, (bf16*)vhi, (bf16*)vlo, 512, 768, M_, 1.0f);

    // Attention
    flash_bf3<<<dim3(N_ / 128, H_, B_), 256, FLASH_SMEM>>>(
        (const bf16*)qhi, (const bf16*)qlo, (const bf16*)khi, (const bf16*)klo,
        (const bf16*)vhi, (const bf16*)vlo, (bf16*)ohi, (bf16*)olo);

    // Output projection
    gemm_bf3<128, 64, 0><<<dim3(5, 128), 128, GEMM_SMEM>>>(
        (const bf16*)ohi, (const bf16*)olo, (const bf16*)wohi, (const bf16*)wolo,
        bo, out, nullptr, nullptr, 320, 512, 0, 1.0f);
}